// round 2
// baseline (speedup 1.0000x reference)
#include <cuda_runtime.h>

#define Bx 16
#define NN 256
#define MM 256
#define DD 256
#define UU 256

// scratch (device globals — no allocations allowed)
__device__ float g_encpT[Bx * UU * MM];  // enc_proj TRANSPOSED [B][U][M]
__device__ float g_decp [Bx * NN * UU];  // dec_proj [B][N][U]
__device__ unsigned int g_tick;

__device__ __forceinline__ float tanh_ap(float x) {
    float y;
    asm("tanh.approx.f32 %0, %1;" : "=f"(y) : "f"(x));
    return y;
}

__global__ void reset_tick() { g_tick = 0u; }

// ---------------------------------------------------------------------------
// Fused projection GEMM. z=0: enc@W1+b1 -> g_encpT (transposed [B,U,M])
//                        z=1: dec@W2+b2 -> g_decp  ([B,N,U])
// 64x64 tile, BK=16, 256 threads, 4x4 microtile. Grid (4, 64, 2) = 512 blocks.
// ---------------------------------------------------------------------------
__global__ __launch_bounds__(256) void proj_gemm(const float* __restrict__ enc,
                                                 const float* __restrict__ dec,
                                                 const float* __restrict__ W1,
                                                 const float* __restrict__ b1,
                                                 const float* __restrict__ W2,
                                                 const float* __restrict__ b2)
{
    const int z = blockIdx.z;
    const float* A    = z ? dec : enc;
    const float* W    = z ? W2  : W1;
    const float* bias = z ? b2  : b1;

    __shared__ float As[16 * 68];   // transposed A tile
    __shared__ float Ws[16 * 64];   // W tile row-major

    const int tid = threadIdx.x;
    const int tm = tid >> 4;        // 0..15
    const int tn = tid & 15;        // 0..15
    const int row0 = blockIdx.y * 64;
    const int col0 = blockIdx.x * 64;

    const int ar  = tid >> 2;       // 0..63
    const int ac4 = tid & 3;        // 0..3
    const int wr  = tid >> 4;       // 0..15
    const int wc4 = tid & 15;       // 0..15

    float c[4][4] = {};

    for (int kt = 0; kt < 256; kt += 16) {
        float4 a = *(const float4*)(A + (size_t)(row0 + ar) * 256 + kt + ac4 * 4);
        float4 w = *(const float4*)(W + (size_t)(kt + wr) * 256 + col0 + wc4 * 4);
        __syncthreads();
        As[(ac4 * 4 + 0) * 68 + ar] = a.x;
        As[(ac4 * 4 + 1) * 68 + ar] = a.y;
        As[(ac4 * 4 + 2) * 68 + ar] = a.z;
        As[(ac4 * 4 + 3) * 68 + ar] = a.w;
        *(float4*)(Ws + wr * 64 + wc4 * 4) = w;
        __syncthreads();
        #pragma unroll
        for (int k = 0; k < 16; k++) {
            float4 av = *(float4*)(As + k * 68 + tm * 4);
            float4 wv = *(float4*)(Ws + k * 64 + tn * 4);
            float am[4] = {av.x, av.y, av.z, av.w};
            float wn[4] = {wv.x, wv.y, wv.z, wv.w};
            #pragma unroll
            for (int i = 0; i < 4; i++)
                #pragma unroll
                for (int j = 0; j < 4; j++)
                    c[i][j] = fmaf(am[i], wn[j], c[i][j]);
        }
    }

    float4 bv = *(const float4*)(bias + col0 + tn * 4);
    float bb[4] = {bv.x, bv.y, bv.z, bv.w};

    if (z) {
        // normal store to g_decp: rows are (b*256+n)
        #pragma unroll
        for (int i = 0; i < 4; i++) {
            float4 o;
            o.x = c[i][0] + bb[0];
            o.y = c[i][1] + bb[1];
            o.z = c[i][2] + bb[2];
            o.w = c[i][3] + bb[3];
            *(float4*)(g_decp + (size_t)(row0 + tm * 4 + i) * 256 + col0 + tn * 4) = o;
        }
    } else {
        // transposed store to g_encpT[b][u][m]; rows r = b*256 + m
        const int b  = row0 >> 8;
        const int m0 = (row0 & 255) + tm * 4;
        #pragma unroll
        for (int j = 0; j < 4; j++) {
            const int u = col0 + tn * 4 + j;
            float4 o;
            o.x = c[0][j] + bb[j];
            o.y = c[1][j] + bb[j];
            o.z = c[2][j] + bb[j];
            o.w = c[3][j] + bb[j];
            *(float4*)(g_encpT + (size_t)b * 65536 + (size_t)u * 256 + m0) = o;
        }
    }
}

// ---------------------------------------------------------------------------
// Persistent fused attention: logits (tanh core) + softmax + context.
// Tile = (b, 4 n-rows). 1024 tiles, dynamic tickets. 128 threads = 4 warps,
// 1 n-row per warp. Lanes span m: lane holds logits for m = 4*lane..4*lane+3
// and 128+4*lane.. (no per-m shuffle reduction). enc_proj is transposed so
// the inner loop reads sE[u][m] coalesced; dec/v are scalar broadcasts.
// ---------------------------------------------------------------------------
__global__ __launch_bounds__(128) void attn_kernel(const float* __restrict__ enc,
                                                   const float* __restrict__ v_w,
                                                   float* __restrict__ out_ctx,
                                                   float* __restrict__ out_w)
{
    __shared__ float sE[32 * 256];   // [32 u][256 m]  or  [32 m][256 d]
    __shared__ float sD[4 * 256];    // dec_proj rows for this tile
    __shared__ float sW[4 * 256];    // softmax weights
    __shared__ float sV[256];        // v_w
    __shared__ unsigned int sTick;

    const int tid  = threadIdx.x;
    const int warp = tid >> 5;      // 0..3  -> local n row
    const int lane = tid & 31;

    // load v once (read-only across tiles)
    {
        float4* sV4 = (float4*)sV;
        if (tid < 64) sV4[tid] = ((const float4*)v_w)[tid];
    }

    float4* sE4 = (float4*)sE;

    for (;;) {
        if (tid == 0) sTick = atomicAdd(&g_tick, 1u);
        __syncthreads();                 // also: all warps done with prev tile
        const unsigned int t = sTick;
        if (t >= 1024u) break;

        const int b  = t >> 6;           // 0..15
        const int n0 = (t & 63) * 4;     // tile base row
        const int n  = n0 + warp;

        // stage dec_proj tile (4 x 256)
        {
            const float4* dsrc = (const float4*)(g_decp + (size_t)(b * NN + n0) * UU);
            float4* sD4 = (float4*)sD;
            #pragma unroll
            for (int i = 0; i < 2; i++) sD4[tid + i * 128] = dsrc[tid + i * 128];
        }

        // ---- phase 1: logits ----
        float lg[8] = {0.f, 0.f, 0.f, 0.f, 0.f, 0.f, 0.f, 0.f};
        for (int uc = 0; uc < 8; uc++) {
            __syncthreads();
            const float4* esrc = (const float4*)(g_encpT + (size_t)b * 65536 + (size_t)(uc * 32) * 256);
            #pragma unroll
            for (int i = 0; i < 16; i++) sE4[tid + i * 128] = esrc[tid + i * 128];
            __syncthreads();
            #pragma unroll 4
            for (int uu = 0; uu < 32; uu++) {
                const int u = uc * 32 + uu;
                const float dn = sD[warp * 256 + u];
                const float vu = sV[u];
                float4 ea = sE4[uu * 64 + lane];
                float4 eb = sE4[uu * 64 + 32 + lane];
                lg[0] = fmaf(vu, tanh_ap(ea.x + dn), lg[0]);
                lg[1] = fmaf(vu, tanh_ap(ea.y + dn), lg[1]);
                lg[2] = fmaf(vu, tanh_ap(ea.z + dn), lg[2]);
                lg[3] = fmaf(vu, tanh_ap(ea.w + dn), lg[3]);
                lg[4] = fmaf(vu, tanh_ap(eb.x + dn), lg[4]);
                lg[5] = fmaf(vu, tanh_ap(eb.y + dn), lg[5]);
                lg[6] = fmaf(vu, tanh_ap(eb.z + dn), lg[6]);
                lg[7] = fmaf(vu, tanh_ap(eb.w + dn), lg[7]);
            }
        }

        // ---- phase 2: softmax over m (v_b cancels) ----
        float mx = lg[0];
        #pragma unroll
        for (int k = 1; k < 8; k++) mx = fmaxf(mx, lg[k]);
        #pragma unroll
        for (int o = 16; o > 0; o >>= 1) mx = fmaxf(mx, __shfl_xor_sync(0xFFFFFFFFu, mx, o));
        float s = 0.f;
        #pragma unroll
        for (int k = 0; k < 8; k++) { lg[k] = __expf(lg[k] - mx); s += lg[k]; }
        #pragma unroll
        for (int o = 16; o > 0; o >>= 1) s += __shfl_xor_sync(0xFFFFFFFFu, s, o);
        const float inv = 1.f / s;

        {
            float4 wA, wB;
            wA.x = lg[0] * inv; wA.y = lg[1] * inv; wA.z = lg[2] * inv; wA.w = lg[3] * inv;
            wB.x = lg[4] * inv; wB.y = lg[5] * inv; wB.z = lg[6] * inv; wB.w = lg[7] * inv;
            ((float4*)(sW + warp * 256))[lane]      = wA;
            ((float4*)(sW + warp * 256))[32 + lane] = wB;
            float4* wo = (float4*)(out_w + (size_t)(b * NN + n) * MM);
            wo[lane]      = wA;
            wo[32 + lane] = wB;
        }
        __syncwarp();   // sW row is warp-private; make it visible within warp

        // ---- phase 3: context = weights @ enc ----
        float4 ca = {0.f, 0.f, 0.f, 0.f}, cb = {0.f, 0.f, 0.f, 0.f};
        for (int mc = 0; mc < 8; mc++) {
            __syncthreads();
            const float4* esrc = (const float4*)(enc + (size_t)b * 65536 + (size_t)(mc * 32) * 256);
            #pragma unroll
            for (int i = 0; i < 16; i++) sE4[tid + i * 128] = esrc[tid + i * 128];
            __syncthreads();
            #pragma unroll 4
            for (int mm = 0; mm < 32; mm++) {
                const float w = sW[warp * 256 + mc * 32 + mm];
                float4 ea = sE4[mm * 64 + lane];
                float4 eb = sE4[mm * 64 + 32 + lane];
                ca.x = fmaf(w, ea.x, ca.x);
                ca.y = fmaf(w, ea.y, ca.y);
                ca.z = fmaf(w, ea.z, ca.z);
                ca.w = fmaf(w, ea.w, ca.w);
                cb.x = fmaf(w, eb.x, cb.x);
                cb.y = fmaf(w, eb.y, cb.y);
                cb.z = fmaf(w, eb.z, cb.z);
                cb.w = fmaf(w, eb.w, cb.w);
            }
        }
        {
            float4* co = (float4*)(out_ctx + (size_t)(b * NN + n) * DD);
            co[lane]      = ca;
            co[32 + lane] = cb;
        }
    }
}

extern "C" void kernel_launch(void* const* d_in, const int* in_sizes, int n_in,
                              void* d_out, int out_size)
{
    const float* enc = (const float*)d_in[0];
    const float* dec = (const float*)d_in[1];
    const float* W1  = (const float*)d_in[2];
    const float* b1  = (const float*)d_in[3];
    const float* W2  = (const float*)d_in[4];
    const float* b2  = (const float*)d_in[5];
    const float* vw  = (const float*)d_in[6];
    // d_in[7] = v_b: constant shift, cancels in softmax -> unused.

    float* out_ctx = (float*)d_out;                              // [B,N,D]
    float* out_w   = (float*)d_out + (size_t)Bx * NN * DD;       // [B,N,M,1]

    reset_tick<<<1, 1>>>();
    proj_gemm<<<dim3(4, 64, 2), 256>>>(enc, dec, W1, b1, W2, b2);
    attn_kernel<<<740, 128>>>(enc, vw, out_ctx, out_w);
}

// round 3
// speedup vs baseline: 1.0270x; 1.0270x over previous
#include <cuda_runtime.h>

#define Bx 16
#define NN 256
#define MM 256
#define DD 256
#define UU 256

// scratch (device globals — no allocations allowed)
__device__ float g_encpT[Bx * UU * MM];  // enc_proj TRANSPOSED [B][U][M]
__device__ float g_decp [Bx * NN * UU];  // dec_proj [B][N][U]

__device__ __forceinline__ float tanh_ap(float x) {
    float y;
    asm("tanh.approx.f32 %0, %1;" : "=f"(y) : "f"(x));
    return y;
}

// ---------------------------------------------------------------------------
// Fused projection GEMM. z=0: enc@W1+b1 -> g_encpT (transposed [B,U,M])
//                        z=1: dec@W2+b2 -> g_decp  ([B,N,U])
// 64x64 tile, BK=16, 256 threads, 4x4 microtile. Grid (4, 64, 2) = 512 blocks.
// ---------------------------------------------------------------------------
__global__ __launch_bounds__(256) void proj_gemm(const float* __restrict__ enc,
                                                 const float* __restrict__ dec,
                                                 const float* __restrict__ W1,
                                                 const float* __restrict__ b1,
                                                 const float* __restrict__ W2,
                                                 const float* __restrict__ b2)
{
    const int z = blockIdx.z;
    const float* A    = z ? dec : enc;
    const float* W    = z ? W2  : W1;
    const float* bias = z ? b2  : b1;

    __shared__ float As[16 * 68];   // transposed A tile
    __shared__ float Ws[16 * 64];   // W tile row-major

    const int tid = threadIdx.x;
    const int tm = tid >> 4;        // 0..15
    const int tn = tid & 15;        // 0..15
    const int row0 = blockIdx.y * 64;
    const int col0 = blockIdx.x * 64;

    const int ar  = tid >> 2;       // 0..63
    const int ac4 = tid & 3;        // 0..3
    const int wr  = tid >> 4;       // 0..15
    const int wc4 = tid & 15;       // 0..15

    float c[4][4] = {};

    for (int kt = 0; kt < 256; kt += 16) {
        float4 a = *(const float4*)(A + (size_t)(row0 + ar) * 256 + kt + ac4 * 4);
        float4 w = *(const float4*)(W + (size_t)(kt + wr) * 256 + col0 + wc4 * 4);
        __syncthreads();
        As[(ac4 * 4 + 0) * 68 + ar] = a.x;
        As[(ac4 * 4 + 1) * 68 + ar] = a.y;
        As[(ac4 * 4 + 2) * 68 + ar] = a.z;
        As[(ac4 * 4 + 3) * 68 + ar] = a.w;
        *(float4*)(Ws + wr * 64 + wc4 * 4) = w;
        __syncthreads();
        #pragma unroll
        for (int k = 0; k < 16; k++) {
            float4 av = *(float4*)(As + k * 68 + tm * 4);
            float4 wv = *(float4*)(Ws + k * 64 + tn * 4);
            float am[4] = {av.x, av.y, av.z, av.w};
            float wn[4] = {wv.x, wv.y, wv.z, wv.w};
            #pragma unroll
            for (int i = 0; i < 4; i++)
                #pragma unroll
                for (int j = 0; j < 4; j++)
                    c[i][j] = fmaf(am[i], wn[j], c[i][j]);
        }
    }

    float4 bv = *(const float4*)(bias + col0 + tn * 4);
    float bb[4] = {bv.x, bv.y, bv.z, bv.w};

    if (z) {
        #pragma unroll
        for (int i = 0; i < 4; i++) {
            float4 o;
            o.x = c[i][0] + bb[0];
            o.y = c[i][1] + bb[1];
            o.z = c[i][2] + bb[2];
            o.w = c[i][3] + bb[3];
            *(float4*)(g_decp + (size_t)(row0 + tm * 4 + i) * 256 + col0 + tn * 4) = o;
        }
    } else {
        const int b  = row0 >> 8;
        const int m0 = (row0 & 255) + tm * 4;
        #pragma unroll
        for (int j = 0; j < 4; j++) {
            const int u = col0 + tn * 4 + j;
            float4 o;
            o.x = c[0][j] + bb[j];
            o.y = c[1][j] + bb[j];
            o.z = c[2][j] + bb[j];
            o.w = c[3][j] + bb[j];
            *(float4*)(g_encpT + (size_t)b * 65536 + (size_t)u * 256 + m0) = o;
        }
    }
}

// ---------------------------------------------------------------------------
// Fused attention: logits (tanh core) + softmax + context.
// Block = 8 n-rows of one b. 512 blocks, 128 threads = 4 warps, 2 rows/warp.
// Lanes span m: lane holds logits for m = 4*lane..+3 and 128+4*lane..+3.
// Each staged e-value feeds 2 tanh (2 rows) -> halved SMEM read pressure.
// ---------------------------------------------------------------------------
__global__ __launch_bounds__(128) void attn_kernel(const float* __restrict__ enc,
                                                   const float* __restrict__ v_w,
                                                   float* __restrict__ out_ctx,
                                                   float* __restrict__ out_w)
{
    __shared__ float sE[32 * 256];   // [32 u][256 m]  or  [32 m][256 d]
    __shared__ float sD[8 * 256];    // dec_proj rows for this tile
    __shared__ float sW[8 * 256];    // softmax weights
    __shared__ float sV[256];        // v_w

    const int tid  = threadIdx.x;
    const int warp = tid >> 5;       // 0..3
    const int lane = tid & 31;

    const int b  = blockIdx.x >> 5;          // 0..15
    const int n0 = (blockIdx.x & 31) * 8;    // tile base row
    const int r0 = warp * 2;                 // local rows
    const int r1 = r0 + 1;
    const int gn0 = n0 + r0;
    const int gn1 = n0 + r1;

    // stage v and dec_proj tile
    {
        float4* sV4 = (float4*)sV;
        if (tid < 64) sV4[tid] = ((const float4*)v_w)[tid];
        const float4* dsrc = (const float4*)(g_decp + (size_t)(b * NN + n0) * UU);
        float4* sD4 = (float4*)sD;
        #pragma unroll
        for (int i = 0; i < 4; i++) sD4[tid + i * 128] = dsrc[tid + i * 128];
    }

    float4* sE4 = (float4*)sE;

    // ---- phase 1: logits ----
    float lg0[8] = {0,0,0,0,0,0,0,0};
    float lg1[8] = {0,0,0,0,0,0,0,0};
    for (int uc = 0; uc < 8; uc++) {
        __syncthreads();
        const float4* esrc = (const float4*)(g_encpT + (size_t)b * 65536 + (size_t)(uc * 32) * 256);
        #pragma unroll
        for (int i = 0; i < 16; i++) sE4[tid + i * 128] = esrc[tid + i * 128];
        __syncthreads();
        #pragma unroll 2
        for (int uu = 0; uu < 32; uu++) {
            const int u = uc * 32 + uu;
            const float dn0 = sD[r0 * 256 + u];
            const float dn1 = sD[r1 * 256 + u];
            const float vu  = sV[u];
            float4 ea = sE4[uu * 64 + lane];
            float4 eb = sE4[uu * 64 + 32 + lane];
            lg0[0] = fmaf(vu, tanh_ap(ea.x + dn0), lg0[0]);
            lg0[1] = fmaf(vu, tanh_ap(ea.y + dn0), lg0[1]);
            lg0[2] = fmaf(vu, tanh_ap(ea.z + dn0), lg0[2]);
            lg0[3] = fmaf(vu, tanh_ap(ea.w + dn0), lg0[3]);
            lg0[4] = fmaf(vu, tanh_ap(eb.x + dn0), lg0[4]);
            lg0[5] = fmaf(vu, tanh_ap(eb.y + dn0), lg0[5]);
            lg0[6] = fmaf(vu, tanh_ap(eb.z + dn0), lg0[6]);
            lg0[7] = fmaf(vu, tanh_ap(eb.w + dn0), lg0[7]);
            lg1[0] = fmaf(vu, tanh_ap(ea.x + dn1), lg1[0]);
            lg1[1] = fmaf(vu, tanh_ap(ea.y + dn1), lg1[1]);
            lg1[2] = fmaf(vu, tanh_ap(ea.z + dn1), lg1[2]);
            lg1[3] = fmaf(vu, tanh_ap(ea.w + dn1), lg1[3]);
            lg1[4] = fmaf(vu, tanh_ap(eb.x + dn1), lg1[4]);
            lg1[5] = fmaf(vu, tanh_ap(eb.y + dn1), lg1[5]);
            lg1[6] = fmaf(vu, tanh_ap(eb.z + dn1), lg1[6]);
            lg1[7] = fmaf(vu, tanh_ap(eb.w + dn1), lg1[7]);
        }
    }

    // ---- phase 2: softmax over m (v_b cancels) ----
    #pragma unroll
    for (int r = 0; r < 2; r++) {
        float* lg = r ? lg1 : lg0;
        const int ln = r ? r1 : r0;
        const int gn = n0 + ln;
        float mx = lg[0];
        #pragma unroll
        for (int k = 1; k < 8; k++) mx = fmaxf(mx, lg[k]);
        #pragma unroll
        for (int o = 16; o > 0; o >>= 1) mx = fmaxf(mx, __shfl_xor_sync(0xFFFFFFFFu, mx, o));
        float s = 0.f;
        #pragma unroll
        for (int k = 0; k < 8; k++) { lg[k] = __expf(lg[k] - mx); s += lg[k]; }
        #pragma unroll
        for (int o = 16; o > 0; o >>= 1) s += __shfl_xor_sync(0xFFFFFFFFu, s, o);
        const float inv = 1.f / s;

        float4 wA, wB;
        wA.x = lg[0] * inv; wA.y = lg[1] * inv; wA.z = lg[2] * inv; wA.w = lg[3] * inv;
        wB.x = lg[4] * inv; wB.y = lg[5] * inv; wB.z = lg[6] * inv; wB.w = lg[7] * inv;
        ((float4*)(sW + ln * 256))[lane]      = wA;
        ((float4*)(sW + ln * 256))[32 + lane] = wB;
        float4* wo = (float4*)(out_w + (size_t)(b * NN + gn) * MM);
        wo[lane]      = wA;
        wo[32 + lane] = wB;
    }
    __syncwarp();   // sW rows are warp-private in phase 3

    // ---- phase 3: context = weights @ enc (lanes span d) ----
    float4 c0a = {0,0,0,0}, c0b = {0,0,0,0};
    float4 c1a = {0,0,0,0}, c1b = {0,0,0,0};
    for (int mc = 0; mc < 8; mc++) {
        __syncthreads();
        const float4* esrc = (const float4*)(enc + (size_t)b * 65536 + (size_t)(mc * 32) * 256);
        #pragma unroll
        for (int i = 0; i < 16; i++) sE4[tid + i * 128] = esrc[tid + i * 128];
        __syncthreads();
        #pragma unroll 4
        for (int mm = 0; mm < 32; mm++) {
            const int m = mc * 32 + mm;
            const float w0 = sW[r0 * 256 + m];
            const float w1 = sW[r1 * 256 + m];
            float4 ea = sE4[mm * 64 + lane];
            float4 eb = sE4[mm * 64 + 32 + lane];
            c0a.x = fmaf(w0, ea.x, c0a.x);
            c0a.y = fmaf(w0, ea.y, c0a.y);
            c0a.z = fmaf(w0, ea.z, c0a.z);
            c0a.w = fmaf(w0, ea.w, c0a.w);
            c0b.x = fmaf(w0, eb.x, c0b.x);
            c0b.y = fmaf(w0, eb.y, c0b.y);
            c0b.z = fmaf(w0, eb.z, c0b.z);
            c0b.w = fmaf(w0, eb.w, c0b.w);
            c1a.x = fmaf(w1, ea.x, c1a.x);
            c1a.y = fmaf(w1, ea.y, c1a.y);
            c1a.z = fmaf(w1, ea.z, c1a.z);
            c1a.w = fmaf(w1, ea.w, c1a.w);
            c1b.x = fmaf(w1, eb.x, c1b.x);
            c1b.y = fmaf(w1, eb.y, c1b.y);
            c1b.z = fmaf(w1, eb.z, c1b.z);
            c1b.w = fmaf(w1, eb.w, c1b.w);
        }
    }
    {
        float4* o0 = (float4*)(out_ctx + (size_t)(b * NN + gn0) * DD);
        o0[lane]      = c0a;
        o0[32 + lane] = c0b;
        float4* o1 = (float4*)(out_ctx + (size_t)(b * NN + gn1) * DD);
        o1[lane]      = c1a;
        o1[32 + lane] = c1b;
    }
}

extern "C" void kernel_launch(void* const* d_in, const int* in_sizes, int n_in,
                              void* d_out, int out_size)
{
    const float* enc = (const float*)d_in[0];
    const float* dec = (const float*)d_in[1];
    const float* W1  = (const float*)d_in[2];
    const float* b1  = (const float*)d_in[3];
    const float* W2  = (const float*)d_in[4];
    const float* b2  = (const float*)d_in[5];
    const float* vw  = (const float*)d_in[6];
    // d_in[7] = v_b: constant shift, cancels in softmax -> unused.

    float* out_ctx = (float*)d_out;                              // [B,N,D]
    float* out_w   = (float*)d_out + (size_t)Bx * NN * DD;       // [B,N,M,1]

    proj_gemm<<<dim3(4, 64, 2), 256>>>(enc, dec, W1, b1, W2, b2);
    attn_kernel<<<512, 128>>>(enc, vw, out_ctx, out_w);
}

// round 4
// speedup vs baseline: 1.1193x; 1.0898x over previous
#include <cuda_runtime.h>

#define Bx 16
#define NN 256
#define MM 256
#define DD 256
#define UU 256

// scratch (device globals — no allocations allowed)
__device__ float g_encpT[Bx * UU * MM];  // enc_proj TRANSPOSED [B][U][M]
__device__ float g_decp [Bx * NN * UU];  // dec_proj [B][N][U]

__device__ __forceinline__ float tanh_ap(float x) {
    float y;
    asm("tanh.approx.f32 %0, %1;" : "=f"(y) : "f"(x));
    return y;
}

// ---------------------------------------------------------------------------
// Fused projection GEMM. z=0: enc@W1+b1 -> g_encpT (transposed [B,U,M])
//                        z=1: dec@W2+b2 -> g_decp  ([B,N,U])
// ---------------------------------------------------------------------------
__global__ __launch_bounds__(256) void proj_gemm(const float* __restrict__ enc,
                                                 const float* __restrict__ dec,
                                                 const float* __restrict__ W1,
                                                 const float* __restrict__ b1,
                                                 const float* __restrict__ W2,
                                                 const float* __restrict__ b2)
{
    const int z = blockIdx.z;
    const float* A    = z ? dec : enc;
    const float* W    = z ? W2  : W1;
    const float* bias = z ? b2  : b1;

    __shared__ float As[16 * 68];
    __shared__ float Ws[16 * 64];

    const int tid = threadIdx.x;
    const int tm = tid >> 4;
    const int tn = tid & 15;
    const int row0 = blockIdx.y * 64;
    const int col0 = blockIdx.x * 64;

    const int ar  = tid >> 2;
    const int ac4 = tid & 3;
    const int wr  = tid >> 4;
    const int wc4 = tid & 15;

    float c[4][4] = {};

    for (int kt = 0; kt < 256; kt += 16) {
        float4 a = *(const float4*)(A + (size_t)(row0 + ar) * 256 + kt + ac4 * 4);
        float4 w = *(const float4*)(W + (size_t)(kt + wr) * 256 + col0 + wc4 * 4);
        __syncthreads();
        As[(ac4 * 4 + 0) * 68 + ar] = a.x;
        As[(ac4 * 4 + 1) * 68 + ar] = a.y;
        As[(ac4 * 4 + 2) * 68 + ar] = a.z;
        As[(ac4 * 4 + 3) * 68 + ar] = a.w;
        *(float4*)(Ws + wr * 64 + wc4 * 4) = w;
        __syncthreads();
        #pragma unroll
        for (int k = 0; k < 16; k++) {
            float4 av = *(float4*)(As + k * 68 + tm * 4);
            float4 wv = *(float4*)(Ws + k * 64 + tn * 4);
            float am[4] = {av.x, av.y, av.z, av.w};
            float wn[4] = {wv.x, wv.y, wv.z, wv.w};
            #pragma unroll
            for (int i = 0; i < 4; i++)
                #pragma unroll
                for (int j = 0; j < 4; j++)
                    c[i][j] = fmaf(am[i], wn[j], c[i][j]);
        }
    }

    float4 bv = *(const float4*)(bias + col0 + tn * 4);
    float bb[4] = {bv.x, bv.y, bv.z, bv.w};

    if (z) {
        #pragma unroll
        for (int i = 0; i < 4; i++) {
            float4 o;
            o.x = c[i][0] + bb[0];
            o.y = c[i][1] + bb[1];
            o.z = c[i][2] + bb[2];
            o.w = c[i][3] + bb[3];
            *(float4*)(g_decp + (size_t)(row0 + tm * 4 + i) * 256 + col0 + tn * 4) = o;
        }
    } else {
        const int b  = row0 >> 8;
        const int m0 = (row0 & 255) + tm * 4;
        #pragma unroll
        for (int j = 0; j < 4; j++) {
            const int u = col0 + tn * 4 + j;
            float4 o;
            o.x = c[0][j] + bb[j];
            o.y = c[1][j] + bb[j];
            o.z = c[2][j] + bb[j];
            o.w = c[3][j] + bb[j];
            *(float4*)(g_encpT + (size_t)b * 65536 + (size_t)u * 256 + m0) = o;
        }
    }
}

// ---------------------------------------------------------------------------
// Fused attention. Block = 8 n-rows of one b, 512 blocks, 256 threads = 8 warps.
// Warp halves split the contraction axis: warps 0-3 = rows {2w,2w+1} over
// u (or m) in [0,128); warps 4-7 = same rows over [128,256). Partials are
// exchanged through SMEM (aliased onto the staging buffer). 49KB smem ->
// 4 blocks/SM, 32 warps/SM.
// ---------------------------------------------------------------------------
__global__ __launch_bounds__(256, 4) void attn_kernel(const float* __restrict__ enc,
                                                      const float* __restrict__ v_w,
                                                      float* __restrict__ out_ctx,
                                                      float* __restrict__ out_w)
{
    __shared__ float4 sE4[2048];      // 32KB staging: [32 rows][64 float4]
    __shared__ float sD[8 * 256];     // dec_proj rows (8KB)
    __shared__ float sW[8 * 256];     // softmax weights (8KB)
    __shared__ float sV[256];         // v_w (1KB)
    float* sP = (float*)sE4;          // alias: partial-exchange buffer

    const int tid  = threadIdx.x;
    const int warp = tid >> 5;
    const int lane = tid & 31;
    const int h    = warp >> 2;       // 0: axis [0,128)   1: axis [128,256)
    const int wl   = warp & 3;
    const int r0   = wl * 2;
    const int r1   = r0 + 1;

    const int b  = blockIdx.x >> 5;          // 0..15
    const int n0 = (blockIdx.x & 31) * 8;    // tile base row
    const int gn0 = n0 + r0;
    const int gn1 = n0 + r1;

    // stage v and dec_proj tile
    {
        float4* sV4 = (float4*)sV;
        if (tid < 64) sV4[tid] = ((const float4*)v_w)[tid];
        const float4* dsrc = (const float4*)(g_decp + (size_t)(b * NN + n0) * UU);
        float4* sD4 = (float4*)sD;
        sD4[tid] = dsrc[tid];
        sD4[tid + 256] = dsrc[tid + 256];
    }

    // ---- phase 1: logits (u split across warp halves) ----
    float lg0[8] = {0,0,0,0,0,0,0,0};
    float lg1[8] = {0,0,0,0,0,0,0,0};
    {
        const float* dRow0 = sD + r0 * 256 + h * 128;
        const float* dRow1 = sD + r1 * 256 + h * 128;
        const float* vHalf = sV + h * 128;
        const float4* eb4 = (const float4*)(g_encpT + (size_t)b * 65536);

        for (int s = 0; s < 8; s++) {
            __syncthreads();
            #pragma unroll
            for (int t = 0; t < 8; t++) {
                int idx = tid + t * 256;
                int r = idx >> 6, c = idx & 63;
                int u = s * 16 + r + ((r < 16) ? 0 : 112);   // rows 16-31 hold u+128
                sE4[idx] = eb4[u * 64 + c];
            }
            __syncthreads();
            #pragma unroll 2
            for (int j = 0; j < 16; j++) {
                const int ul = s * 16 + j;
                const float dn0 = dRow0[ul];
                const float dn1 = dRow1[ul];
                const float vu  = vHalf[ul];
                float4 ea = sE4[(h * 16 + j) * 64 + lane];
                float4 eb = sE4[(h * 16 + j) * 64 + 32 + lane];
                lg0[0] = fmaf(vu, tanh_ap(ea.x + dn0), lg0[0]);
                lg0[1] = fmaf(vu, tanh_ap(ea.y + dn0), lg0[1]);
                lg0[2] = fmaf(vu, tanh_ap(ea.z + dn0), lg0[2]);
                lg0[3] = fmaf(vu, tanh_ap(ea.w + dn0), lg0[3]);
                lg0[4] = fmaf(vu, tanh_ap(eb.x + dn0), lg0[4]);
                lg0[5] = fmaf(vu, tanh_ap(eb.y + dn0), lg0[5]);
                lg0[6] = fmaf(vu, tanh_ap(eb.z + dn0), lg0[6]);
                lg0[7] = fmaf(vu, tanh_ap(eb.w + dn0), lg0[7]);
                lg1[0] = fmaf(vu, tanh_ap(ea.x + dn1), lg1[0]);
                lg1[1] = fmaf(vu, tanh_ap(ea.y + dn1), lg1[1]);
                lg1[2] = fmaf(vu, tanh_ap(ea.z + dn1), lg1[2]);
                lg1[3] = fmaf(vu, tanh_ap(ea.w + dn1), lg1[3]);
                lg1[4] = fmaf(vu, tanh_ap(eb.x + dn1), lg1[4]);
                lg1[5] = fmaf(vu, tanh_ap(eb.y + dn1), lg1[5]);
                lg1[6] = fmaf(vu, tanh_ap(eb.z + dn1), lg1[6]);
                lg1[7] = fmaf(vu, tanh_ap(eb.w + dn1), lg1[7]);
            }
        }
    }

    // ---- exchange u-partials, softmax (low warps), write weights ----
    __syncthreads();                       // sE free -> sP usable
    if (h == 1) {
        float4* p0 = (float4*)(sP + r0 * 256);
        float4* p1 = (float4*)(sP + r1 * 256);
        p0[lane]      = make_float4(lg0[0], lg0[1], lg0[2], lg0[3]);
        p0[32 + lane] = make_float4(lg0[4], lg0[5], lg0[6], lg0[7]);
        p1[lane]      = make_float4(lg1[0], lg1[1], lg1[2], lg1[3]);
        p1[32 + lane] = make_float4(lg1[4], lg1[5], lg1[6], lg1[7]);
    }
    __syncthreads();
    if (h == 0) {
        {
            float4 q;
            q = ((float4*)(sP + r0 * 256))[lane];
            lg0[0] += q.x; lg0[1] += q.y; lg0[2] += q.z; lg0[3] += q.w;
            q = ((float4*)(sP + r0 * 256))[32 + lane];
            lg0[4] += q.x; lg0[5] += q.y; lg0[6] += q.z; lg0[7] += q.w;
            q = ((float4*)(sP + r1 * 256))[lane];
            lg1[0] += q.x; lg1[1] += q.y; lg1[2] += q.z; lg1[3] += q.w;
            q = ((float4*)(sP + r1 * 256))[32 + lane];
            lg1[4] += q.x; lg1[5] += q.y; lg1[6] += q.z; lg1[7] += q.w;
        }
        #pragma unroll
        for (int r = 0; r < 2; r++) {
            float* lg = r ? lg1 : lg0;
            const int ln = r ? r1 : r0;
            const int gn = n0 + ln;
            float mx = lg[0];
            #pragma unroll
            for (int k = 1; k < 8; k++) mx = fmaxf(mx, lg[k]);
            #pragma unroll
            for (int o = 16; o > 0; o >>= 1) mx = fmaxf(mx, __shfl_xor_sync(0xFFFFFFFFu, mx, o));
            float sum = 0.f;
            #pragma unroll
            for (int k = 0; k < 8; k++) { lg[k] = __expf(lg[k] - mx); sum += lg[k]; }
            #pragma unroll
            for (int o = 16; o > 0; o >>= 1) sum += __shfl_xor_sync(0xFFFFFFFFu, sum, o);
            const float inv = 1.f / sum;

            float4 wA, wB;
            wA.x = lg[0] * inv; wA.y = lg[1] * inv; wA.z = lg[2] * inv; wA.w = lg[3] * inv;
            wB.x = lg[4] * inv; wB.y = lg[5] * inv; wB.z = lg[6] * inv; wB.w = lg[7] * inv;
            ((float4*)(sW + ln * 256))[lane]      = wA;
            ((float4*)(sW + ln * 256))[32 + lane] = wB;
            float4* wo = (float4*)(out_w + (size_t)(b * NN + gn) * MM);
            wo[lane]      = wA;
            wo[32 + lane] = wB;
        }
    }

    // ---- phase 3: context (m split across warp halves; lanes span d) ----
    float4 c0a = {0,0,0,0}, c0b = {0,0,0,0};
    float4 c1a = {0,0,0,0}, c1b = {0,0,0,0};
    {
        const float* w0p = sW + r0 * 256 + h * 128;
        const float* w1p = sW + r1 * 256 + h * 128;
        const float4* en4 = (const float4*)(enc + (size_t)b * 65536);

        for (int s = 0; s < 8; s++) {
            __syncthreads();
            #pragma unroll
            for (int t = 0; t < 8; t++) {
                int idx = tid + t * 256;
                int r = idx >> 6, c = idx & 63;
                int m = s * 16 + r + ((r < 16) ? 0 : 112);
                sE4[idx] = en4[m * 64 + c];
            }
            __syncthreads();
            #pragma unroll 4
            for (int j = 0; j < 16; j++) {
                const float w0 = w0p[s * 16 + j];
                const float w1 = w1p[s * 16 + j];
                float4 ea = sE4[(h * 16 + j) * 64 + lane];
                float4 eb = sE4[(h * 16 + j) * 64 + 32 + lane];
                c0a.x = fmaf(w0, ea.x, c0a.x);
                c0a.y = fmaf(w0, ea.y, c0a.y);
                c0a.z = fmaf(w0, ea.z, c0a.z);
                c0a.w = fmaf(w0, ea.w, c0a.w);
                c0b.x = fmaf(w0, eb.x, c0b.x);
                c0b.y = fmaf(w0, eb.y, c0b.y);
                c0b.z = fmaf(w0, eb.z, c0b.z);
                c0b.w = fmaf(w0, eb.w, c0b.w);
                c1a.x = fmaf(w1, ea.x, c1a.x);
                c1a.y = fmaf(w1, ea.y, c1a.y);
                c1a.z = fmaf(w1, ea.z, c1a.z);
                c1a.w = fmaf(w1, ea.w, c1a.w);
                c1b.x = fmaf(w1, eb.x, c1b.x);
                c1b.y = fmaf(w1, eb.y, c1b.y);
                c1b.z = fmaf(w1, eb.z, c1b.z);
                c1b.w = fmaf(w1, eb.w, c1b.w);
            }
        }
    }

    // ---- exchange m-partials, store context ----
    __syncthreads();                       // sE free -> sP usable
    if (h == 1) {
        float4* p0 = (float4*)(sP + r0 * 256);
        float4* p1 = (float4*)(sP + r1 * 256);
        p0[lane]      = c0a;
        p0[32 + lane] = c0b;
        p1[lane]      = c1a;
        p1[32 + lane] = c1b;
    }
    __syncthreads();
    if (h == 0) {
        float4 q;
        q = ((float4*)(sP + r0 * 256))[lane];
        c0a.x += q.x; c0a.y += q.y; c0a.z += q.z; c0a.w += q.w;
        q = ((float4*)(sP + r0 * 256))[32 + lane];
        c0b.x += q.x; c0b.y += q.y; c0b.z += q.z; c0b.w += q.w;
        q = ((float4*)(sP + r1 * 256))[lane];
        c1a.x += q.x; c1a.y += q.y; c1a.z += q.z; c1a.w += q.w;
        q = ((float4*)(sP + r1 * 256))[32 + lane];
        c1b.x += q.x; c1b.y += q.y; c1b.z += q.z; c1b.w += q.w;

        float4* o0 = (float4*)(out_ctx + (size_t)(b * NN + gn0) * DD);
        o0[lane]      = c0a;
        o0[32 + lane] = c0b;
        float4* o1 = (float4*)(out_ctx + (size_t)(b * NN + gn1) * DD);
        o1[lane]      = c1a;
        o1[32 + lane] = c1b;
    }
}

extern "C" void kernel_launch(void* const* d_in, const int* in_sizes, int n_in,
                              void* d_out, int out_size)
{
    const float* enc = (const float*)d_in[0];
    const float* dec = (const float*)d_in[1];
    const float* W1  = (const float*)d_in[2];
    const float* b1  = (const float*)d_in[3];
    const float* W2  = (const float*)d_in[4];
    const float* b2  = (const float*)d_in[5];
    const float* vw  = (const float*)d_in[6];
    // d_in[7] = v_b: constant shift, cancels in softmax -> unused.

    float* out_ctx = (float*)d_out;                              // [B,N,D]
    float* out_w   = (float*)d_out + (size_t)Bx * NN * DD;       // [B,N,M,1]

    proj_gemm<<<dim3(4, 64, 2), 256>>>(enc, dec, W1, b1, W2, b2);
    attn_kernel<<<512, 256>>>(enc, vw, out_ctx, out_w);
}

// round 5
// speedup vs baseline: 1.2436x; 1.1111x over previous
#include <cuda_runtime.h>

#define Bx 16
#define NN 256
#define MM 256
#define DD 256
#define UU 256

typedef unsigned long long u64;

// scratch (device globals — no allocations allowed)
__device__ float g_encpT[Bx * UU * MM];  // enc_proj TRANSPOSED [B][U][M]
__device__ float g_decp [Bx * NN * UU];  // dec_proj [B][N][U]

__device__ __forceinline__ float tanh_ap(float x) {
    float y;
    asm("tanh.approx.f32 %0, %1;" : "=f"(y) : "f"(x));
    return y;
}
__device__ __forceinline__ u64 pk2(float lo, float hi) {
    u64 r;
    asm("mov.b64 %0, {%1, %2};" : "=l"(r) : "f"(lo), "f"(hi));
    return r;
}
__device__ __forceinline__ void upk2(u64 v, float& lo, float& hi) {
    asm("mov.b64 {%0, %1}, %2;" : "=f"(lo), "=f"(hi) : "l"(v));
}
__device__ __forceinline__ u64 ffma2(u64 a, u64 b, u64 c) {
    u64 d;
    asm("fma.rn.f32x2 %0, %1, %2, %3;" : "=l"(d) : "l"(a), "l"(b), "l"(c));
    return d;
}
__device__ __forceinline__ void cpa16(void* smem_dst, const void* gsrc) {
    unsigned sa = (unsigned)__cvta_generic_to_shared(smem_dst);
    asm volatile("cp.async.cg.shared.global [%0], [%1], 16;" :: "r"(sa), "l"(gsrc));
}
#define CPA_COMMIT asm volatile("cp.async.commit_group;")
#define CPA_WAIT1  asm volatile("cp.async.wait_group 1;")

// ---------------------------------------------------------------------------
// Fused projection GEMM (f32x2 core). z=0: enc@W1+b1 -> g_encpT ([B,U,M])
//                                     z=1: dec@W2+b2 -> g_decp  ([B,N,U])
// ---------------------------------------------------------------------------
__global__ __launch_bounds__(256) void proj_gemm(const float* __restrict__ enc,
                                                 const float* __restrict__ dec,
                                                 const float* __restrict__ W1,
                                                 const float* __restrict__ b1,
                                                 const float* __restrict__ W2,
                                                 const float* __restrict__ b2)
{
    const int z = blockIdx.z;
    const float* A    = z ? dec : enc;
    const float* W    = z ? W2  : W1;
    const float* bias = z ? b2  : b1;

    __shared__ float As[16 * 68];
    __shared__ float Ws[16 * 64];

    const int tid = threadIdx.x;
    const int tm = tid >> 4;
    const int tn = tid & 15;
    const int row0 = blockIdx.y * 64;
    const int col0 = blockIdx.x * 64;

    const int ar  = tid >> 2;
    const int ac4 = tid & 3;
    const int wr  = tid >> 4;
    const int wc4 = tid & 15;

    u64 c2[4][2] = {};

    for (int kt = 0; kt < 256; kt += 16) {
        float4 a = *(const float4*)(A + (size_t)(row0 + ar) * 256 + kt + ac4 * 4);
        float4 w = *(const float4*)(W + (size_t)(kt + wr) * 256 + col0 + wc4 * 4);
        __syncthreads();
        As[(ac4 * 4 + 0) * 68 + ar] = a.x;
        As[(ac4 * 4 + 1) * 68 + ar] = a.y;
        As[(ac4 * 4 + 2) * 68 + ar] = a.z;
        As[(ac4 * 4 + 3) * 68 + ar] = a.w;
        *(float4*)(Ws + wr * 64 + wc4 * 4) = w;
        __syncthreads();
        #pragma unroll
        for (int k = 0; k < 16; k++) {
            float4 av = *(float4*)(As + k * 68 + tm * 4);
            float4 wv = *(float4*)(Ws + k * 64 + tn * 4);
            u64 w01 = pk2(wv.x, wv.y);
            u64 w23 = pk2(wv.z, wv.w);
            float am[4] = {av.x, av.y, av.z, av.w};
            #pragma unroll
            for (int i = 0; i < 4; i++) {
                u64 aa = pk2(am[i], am[i]);
                c2[i][0] = ffma2(aa, w01, c2[i][0]);
                c2[i][1] = ffma2(aa, w23, c2[i][1]);
            }
        }
    }

    float4 bv = *(const float4*)(bias + col0 + tn * 4);
    float bb[4] = {bv.x, bv.y, bv.z, bv.w};
    float c[4][4];
    #pragma unroll
    for (int i = 0; i < 4; i++) {
        upk2(c2[i][0], c[i][0], c[i][1]);
        upk2(c2[i][1], c[i][2], c[i][3]);
    }

    if (z) {
        #pragma unroll
        for (int i = 0; i < 4; i++) {
            float4 o;
            o.x = c[i][0] + bb[0];
            o.y = c[i][1] + bb[1];
            o.z = c[i][2] + bb[2];
            o.w = c[i][3] + bb[3];
            *(float4*)(g_decp + (size_t)(row0 + tm * 4 + i) * 256 + col0 + tn * 4) = o;
        }
    } else {
        const int b  = row0 >> 8;
        const int m0 = (row0 & 255) + tm * 4;
        #pragma unroll
        for (int j = 0; j < 4; j++) {
            const int u = col0 + tn * 4 + j;
            float4 o;
            o.x = c[0][j] + bb[j];
            o.y = c[1][j] + bb[j];
            o.z = c[2][j] + bb[j];
            o.w = c[3][j] + bb[j];
            *(float4*)(g_encpT + (size_t)b * 65536 + (size_t)u * 256 + m0) = o;
        }
    }
}

// ---------------------------------------------------------------------------
// Fused attention. Block = 8 n-rows of one b, 512 blocks, 256 threads = 8 warps.
// Warp halves split the contraction axis (u / m); partials exchanged via SMEM.
// Staging is cp.async double-buffered: 16 chunks of 16 rows (8 per half),
// next chunk streams while current computes. Phase 3 uses fma.rn.f32x2.
// ---------------------------------------------------------------------------
__global__ __launch_bounds__(256, 4) void attn_kernel(const float* __restrict__ enc,
                                                      const float* __restrict__ v_w,
                                                      float* __restrict__ out_ctx,
                                                      float* __restrict__ out_w)
{
    __shared__ float4 sB[2][1024];    // 2 x 16KB: [16 rows][64 float4]
    __shared__ float sD[8 * 256];     // dec_proj rows (8KB)
    __shared__ float sW[8 * 256];     // softmax weights (8KB)
    __shared__ float sV[256];         // v_w (1KB)
    float* sP = (float*)sB[1];        // alias: partial-exchange buffer (buf1)

    const int tid  = threadIdx.x;
    const int warp = tid >> 5;
    const int lane = tid & 31;
    const int h    = warp >> 2;       // 0: axis [0,128)   1: axis [128,256)
    const int wl   = warp & 3;
    const int r0   = wl * 2;
    const int r1   = r0 + 1;

    const int b  = blockIdx.x >> 5;
    const int n0 = (blockIdx.x & 31) * 8;
    const int gn0 = n0 + r0;
    const int gn1 = n0 + r1;

    const int pr = tid >> 6;          // prefetch row-group base (0..3)
    const int pc = tid & 63;          // prefetch col

    // stage v and dec_proj tile (plain loads; first barrier covers visibility)
    {
        float4* sV4 = (float4*)sV;
        if (tid < 64) sV4[tid] = ((const float4*)v_w)[tid];
        const float4* dsrc = (const float4*)(g_decp + (size_t)(b * NN + n0) * UU);
        float4* sD4 = (float4*)sD;
        sD4[tid] = dsrc[tid];
        sD4[tid + 256] = dsrc[tid + 256];
    }

    const float4* eb4 = (const float4*)(g_encpT + (size_t)b * 65536);
    const float4* en4 = (const float4*)(enc + (size_t)b * 65536);

    // chunk s covers rows r=0..15: r<8 -> u=s*8+r (low half); r>=8 -> u=128+s*8+(r-8)
    #define PREFETCH(src, s, buf)                                              \
        {                                                                      \
            _Pragma("unroll")                                                  \
            for (int t = 0; t < 4; t++) {                                      \
                int r = pr + t * 4;                                            \
                int u = (s) * 8 + r + ((r < 8) ? 0 : 120);                     \
                cpa16((buf) + r * 64 + pc, (src) + u * 64 + pc);               \
            }                                                                  \
        }

    // ---- phase 1: logits (u split across warp halves) ----
    float lg0[8] = {0,0,0,0,0,0,0,0};
    float lg1[8] = {0,0,0,0,0,0,0,0};
    {
        const float* dRow0 = sD + r0 * 256 + h * 128;
        const float* dRow1 = sD + r1 * 256 + h * 128;
        const float* vHalf = sV + h * 128;

        PREFETCH(eb4, 0, sB[0]);
        CPA_COMMIT;
        for (int s = 0; s < 16; s++) {
            if (s + 1 < 16) PREFETCH(eb4, s + 1, sB[(s + 1) & 1]);
            CPA_COMMIT;
            CPA_WAIT1;
            __syncthreads();
            const float4* buf = sB[s & 1];
            #pragma unroll
            for (int j = 0; j < 8; j++) {
                const int ul = s * 8 + j;
                const float dn0 = dRow0[ul];
                const float dn1 = dRow1[ul];
                const float vu  = vHalf[ul];
                float4 ea = buf[(h * 8 + j) * 64 + lane];
                float4 eb = buf[(h * 8 + j) * 64 + 32 + lane];
                lg0[0] = fmaf(vu, tanh_ap(ea.x + dn0), lg0[0]);
                lg0[1] = fmaf(vu, tanh_ap(ea.y + dn0), lg0[1]);
                lg0[2] = fmaf(vu, tanh_ap(ea.z + dn0), lg0[2]);
                lg0[3] = fmaf(vu, tanh_ap(ea.w + dn0), lg0[3]);
                lg0[4] = fmaf(vu, tanh_ap(eb.x + dn0), lg0[4]);
                lg0[5] = fmaf(vu, tanh_ap(eb.y + dn0), lg0[5]);
                lg0[6] = fmaf(vu, tanh_ap(eb.z + dn0), lg0[6]);
                lg0[7] = fmaf(vu, tanh_ap(eb.w + dn0), lg0[7]);
                lg1[0] = fmaf(vu, tanh_ap(ea.x + dn1), lg1[0]);
                lg1[1] = fmaf(vu, tanh_ap(ea.y + dn1), lg1[1]);
                lg1[2] = fmaf(vu, tanh_ap(ea.z + dn1), lg1[2]);
                lg1[3] = fmaf(vu, tanh_ap(ea.w + dn1), lg1[3]);
                lg1[4] = fmaf(vu, tanh_ap(eb.x + dn1), lg1[4]);
                lg1[5] = fmaf(vu, tanh_ap(eb.y + dn1), lg1[5]);
                lg1[6] = fmaf(vu, tanh_ap(eb.z + dn1), lg1[6]);
                lg1[7] = fmaf(vu, tanh_ap(eb.w + dn1), lg1[7]);
            }
            __syncthreads();
        }
    }

    // overlap: start streaming phase-3 chunk 0 into buf0 while we do the
    // u-partial exchange + softmax in buf1 (= sP).
    PREFETCH(en4, 0, sB[0]);
    CPA_COMMIT;

    // ---- exchange u-partials, softmax (low warps), write weights ----
    if (h == 1) {
        float4* p0 = (float4*)(sP + r0 * 256);
        float4* p1 = (float4*)(sP + r1 * 256);
        p0[lane]      = make_float4(lg0[0], lg0[1], lg0[2], lg0[3]);
        p0[32 + lane] = make_float4(lg0[4], lg0[5], lg0[6], lg0[7]);
        p1[lane]      = make_float4(lg1[0], lg1[1], lg1[2], lg1[3]);
        p1[32 + lane] = make_float4(lg1[4], lg1[5], lg1[6], lg1[7]);
    }
    __syncthreads();
    if (h == 0) {
        {
            float4 q;
            q = ((float4*)(sP + r0 * 256))[lane];
            lg0[0] += q.x; lg0[1] += q.y; lg0[2] += q.z; lg0[3] += q.w;
            q = ((float4*)(sP + r0 * 256))[32 + lane];
            lg0[4] += q.x; lg0[5] += q.y; lg0[6] += q.z; lg0[7] += q.w;
            q = ((float4*)(sP + r1 * 256))[lane];
            lg1[0] += q.x; lg1[1] += q.y; lg1[2] += q.z; lg1[3] += q.w;
            q = ((float4*)(sP + r1 * 256))[32 + lane];
            lg1[4] += q.x; lg1[5] += q.y; lg1[6] += q.z; lg1[7] += q.w;
        }
        #pragma unroll
        for (int r = 0; r < 2; r++) {
            float* lg = r ? lg1 : lg0;
            const int ln = r ? r1 : r0;
            const int gn = n0 + ln;
            float mx = lg[0];
            #pragma unroll
            for (int k = 1; k < 8; k++) mx = fmaxf(mx, lg[k]);
            #pragma unroll
            for (int o = 16; o > 0; o >>= 1) mx = fmaxf(mx, __shfl_xor_sync(0xFFFFFFFFu, mx, o));
            float sum = 0.f;
            #pragma unroll
            for (int k = 0; k < 8; k++) { lg[k] = __expf(lg[k] - mx); sum += lg[k]; }
            #pragma unroll
            for (int o = 16; o > 0; o >>= 1) sum += __shfl_xor_sync(0xFFFFFFFFu, sum, o);
            const float inv = 1.f / sum;

            float4 wA, wB;
            wA.x = lg[0] * inv; wA.y = lg[1] * inv; wA.z = lg[2] * inv; wA.w = lg[3] * inv;
            wB.x = lg[4] * inv; wB.y = lg[5] * inv; wB.z = lg[6] * inv; wB.w = lg[7] * inv;
            ((float4*)(sW + ln * 256))[lane]      = wA;
            ((float4*)(sW + ln * 256))[32 + lane] = wB;
            float4* wo = (float4*)(out_w + (size_t)(b * NN + gn) * MM);
            wo[lane]      = wA;
            wo[32 + lane] = wB;
        }
    }
    __syncthreads();

    // ---- phase 3: context (m split across halves; f32x2 FMA; lanes span d) ----
    u64 c0[4] = {0, 0, 0, 0};   // row r0: d pairs {4l,4l+1},{4l+2,4l+3},{128+4l,..},{128+4l+2,..}
    u64 c1[4] = {0, 0, 0, 0};   // row r1
    {
        const float* w0p = sW + r0 * 256 + h * 128;
        const float* w1p = sW + r1 * 256 + h * 128;

        for (int s = 0; s < 16; s++) {
            if (s + 1 < 16) PREFETCH(en4, s + 1, sB[(s + 1) & 1]);
            CPA_COMMIT;
            CPA_WAIT1;
            __syncthreads();
            const float4* buf = sB[s & 1];
            #pragma unroll
            for (int j = 0; j < 8; j++) {
                const float w0 = w0p[s * 8 + j];
                const float w1 = w1p[s * 8 + j];
                u64 ww0 = pk2(w0, w0);
                u64 ww1 = pk2(w1, w1);
                float4 ea = buf[(h * 8 + j) * 64 + lane];
                float4 eb = buf[(h * 8 + j) * 64 + 32 + lane];
                u64 e0 = pk2(ea.x, ea.y);
                u64 e1 = pk2(ea.z, ea.w);
                u64 e2 = pk2(eb.x, eb.y);
                u64 e3 = pk2(eb.z, eb.w);
                c0[0] = ffma2(ww0, e0, c0[0]);
                c0[1] = ffma2(ww0, e1, c0[1]);
                c0[2] = ffma2(ww0, e2, c0[2]);
                c0[3] = ffma2(ww0, e3, c0[3]);
                c1[0] = ffma2(ww1, e0, c1[0]);
                c1[1] = ffma2(ww1, e1, c1[1]);
                c1[2] = ffma2(ww1, e2, c1[2]);
                c1[3] = ffma2(ww1, e3, c1[3]);
            }
            __syncthreads();
        }
    }

    // ---- exchange m-partials, store context ----
    float4 c0a, c0b, c1a, c1b;
    upk2(c0[0], c0a.x, c0a.y); upk2(c0[1], c0a.z, c0a.w);
    upk2(c0[2], c0b.x, c0b.y); upk2(c0[3], c0b.z, c0b.w);
    upk2(c1[0], c1a.x, c1a.y); upk2(c1[1], c1a.z, c1a.w);
    upk2(c1[2], c1b.x, c1b.y); upk2(c1[3], c1b.z, c1b.w);

    if (h == 1) {
        float4* p0 = (float4*)(sP + r0 * 256);
        float4* p1 = (float4*)(sP + r1 * 256);
        p0[lane]      = c0a;
        p0[32 + lane] = c0b;
        p1[lane]      = c1a;
        p1[32 + lane] = c1b;
    }
    __syncthreads();
    if (h == 0) {
        float4 q;
        q = ((float4*)(sP + r0 * 256))[lane];
        c0a.x += q.x; c0a.y += q.y; c0a.z += q.z; c0a.w += q.w;
        q = ((float4*)(sP + r0 * 256))[32 + lane];
        c0b.x += q.x; c0b.y += q.y; c0b.z += q.z; c0b.w += q.w;
        q = ((float4*)(sP + r1 * 256))[lane];
        c1a.x += q.x; c1a.y += q.y; c1a.z += q.z; c1a.w += q.w;
        q = ((float4*)(sP + r1 * 256))[32 + lane];
        c1b.x += q.x; c1b.y += q.y; c1b.z += q.z; c1b.w += q.w;

        float4* o0 = (float4*)(out_ctx + (size_t)(b * NN + gn0) * DD);
        o0[lane]      = c0a;
        o0[32 + lane] = c0b;
        float4* o1 = (float4*)(out_ctx + (size_t)(b * NN + gn1) * DD);
        o1[lane]      = c1a;
        o1[32 + lane] = c1b;
    }
    #undef PREFETCH
}

extern "C" void kernel_launch(void* const* d_in, const int* in_sizes, int n_in,
                              void* d_out, int out_size)
{
    const float* enc = (const float*)d_in[0];
    const float* dec = (const float*)d_in[1];
    const float* W1  = (const float*)d_in[2];
    const float* b1  = (const float*)d_in[3];
    const float* W2  = (const float*)d_in[4];
    const float* b2  = (const float*)d_in[5];
    const float* vw  = (const float*)d_in[6];
    // d_in[7] = v_b: constant shift, cancels in softmax -> unused.

    float* out_ctx = (float*)d_out;                              // [B,N,D]
    float* out_w   = (float*)d_out + (size_t)Bx * NN * DD;       // [B,N,M,1]

    proj_gemm<<<dim3(4, 64, 2), 256>>>(enc, dec, W1, b1, W2, b2);
    attn_kernel<<<512, 256>>>(enc, vw, out_ctx, out_w);
}